// round 1
// baseline (speedup 1.0000x reference)
#include <cuda_runtime.h>
#include <math.h>

// Problem constants (fixed shapes from reference setup_inputs)
#define B_SZ 4096
#define L_SZ 200
#define D_SZ 256
#define STAT_BLOCKS 64              // row-chunks for BN partial sums
static __device__ __constant__ float kInvB = 1.0f / (float)B_SZ;
#define BN_EPS 1e-5f

// ---- scratch (device globals; no allocation allowed) ----
__device__ float g_pooled[(size_t)B_SZ * D_SZ];   // 4 MB
__device__ float g_z[(size_t)B_SZ * D_SZ];        // 4 MB
__device__ float g_psum[STAT_BLOCKS * D_SZ];
__device__ float g_psq[STAT_BLOCKS * D_SZ];
__device__ float g_scale[D_SZ];
__device__ float g_shift[D_SZ];

// ---- packed f32x2 helpers (Blackwell) ----
__device__ __forceinline__ unsigned long long pk2(float lo, float hi) {
    unsigned long long r;
    asm("mov.b64 %0, {%1, %2};" : "=l"(r) : "f"(lo), "f"(hi));
    return r;
}
__device__ __forceinline__ void upk2(unsigned long long v, float& lo, float& hi) {
    asm("mov.b64 {%0, %1}, %2;" : "=f"(lo), "=f"(hi) : "l"(v));
}
__device__ __forceinline__ unsigned long long fma2(unsigned long long a,
                                                   unsigned long long b,
                                                   unsigned long long c) {
    unsigned long long d;
    asm("fma.rn.f32x2 %0, %1, %2, %3;" : "=l"(d) : "l"(a), "l"(b), "l"(c));
    return d;
}

// ============================================================================
// K1: ragged gather + mean pool.  One CTA per batch row, 256 threads.
// 4 tokens in flight per iteration (tid>>6 selects token, tid&63 selects the
// float4 slice of D=256).  Coalesced 512B/warp within an embedding row.
// ============================================================================
__global__ void __launch_bounds__(256) pool_kernel(const int* __restrict__ tokens,
                                                   const int* __restrict__ lengths,
                                                   const float* __restrict__ emb) {
    const int b = blockIdx.x;
    const int tid = threadIdx.x;
    __shared__ int s_tok[L_SZ];
    const int len = lengths[b];
    for (int i = tid; i < len; i += 256) s_tok[i] = tokens[b * L_SZ + i];
    __syncthreads();

    const int sub = tid >> 6;   // 0..3 : which token of the group of 4
    const int q   = tid & 63;   // which float4 of the 256-wide embedding

    float4 acc = make_float4(0.f, 0.f, 0.f, 0.f);
    #pragma unroll 2
    for (int l = sub; l < len; l += 4) {
        const float4* row = reinterpret_cast<const float4*>(emb + (size_t)s_tok[l] * D_SZ);
        float4 v = __ldg(row + q);
        acc.x += v.x; acc.y += v.y; acc.z += v.z; acc.w += v.w;
    }

    __shared__ float4 s_acc[256];
    s_acc[tid] = acc;
    __syncthreads();
    if (tid < 64) {
        float4 a = s_acc[tid];
        float4 c = s_acc[tid + 64];
        float4 d = s_acc[tid + 128];
        float4 e = s_acc[tid + 192];
        const float inv = 1.0f / (float)len;
        float4 r;
        r.x = (a.x + c.x + d.x + e.x) * inv;
        r.y = (a.y + c.y + d.y + e.y) * inv;
        r.z = (a.z + c.z + d.z + e.z) * inv;
        r.w = (a.w + c.w + d.w + e.w) * inv;
        reinterpret_cast<float4*>(g_pooled + (size_t)b * D_SZ)[tid] = r;
    }
}

// ============================================================================
// K2: z = pooled @ W1^T + b1.   M=4096, N=256, K=256, fp32.
// 64x64 block tile, BK=16, 256 threads, 4x4 per thread via fma.rn.f32x2.
// z[m,n] = sum_k pooled[m,k] * W1[n,k]
// ============================================================================
__global__ void __launch_bounds__(256) gemm_kernel(const float* __restrict__ W1,
                                                   const float* __restrict__ b1) {
    __shared__ float As[16][68];   // As[k][m]  (+4 pad, rows stay 16B aligned)
    __shared__ float Bs[16][68];   // Bs[k][n]

    const int tid = threadIdx.x;
    const int tx = tid & 15, ty = tid >> 4;
    const int m0 = blockIdx.x * 64;
    const int n0 = blockIdx.y * 64;
    const int lr = tid >> 2;            // 0..63 tile row
    const int lk = (tid & 3) << 2;      // 0,4,8,12 k-offset

    unsigned long long c2[4][2];
    #pragma unroll
    for (int i = 0; i < 4; i++) { c2[i][0] = 0ull; c2[i][1] = 0ull; }

    for (int k0 = 0; k0 < D_SZ; k0 += 16) {
        float4 av = *reinterpret_cast<const float4*>(g_pooled + (size_t)(m0 + lr) * D_SZ + k0 + lk);
        float4 bv = *reinterpret_cast<const float4*>(W1 + (size_t)(n0 + lr) * D_SZ + k0 + lk);
        As[lk + 0][lr] = av.x; As[lk + 1][lr] = av.y; As[lk + 2][lr] = av.z; As[lk + 3][lr] = av.w;
        Bs[lk + 0][lr] = bv.x; Bs[lk + 1][lr] = bv.y; Bs[lk + 2][lr] = bv.z; Bs[lk + 3][lr] = bv.w;
        __syncthreads();

        #pragma unroll
        for (int k = 0; k < 16; k++) {
            float4 a  = *reinterpret_cast<const float4*>(&As[k][ty << 2]);
            float4 bq = *reinterpret_cast<const float4*>(&Bs[k][tx << 2]);
            unsigned long long b01 = pk2(bq.x, bq.y);
            unsigned long long b23 = pk2(bq.z, bq.w);
            float aa[4] = {a.x, a.y, a.z, a.w};
            #pragma unroll
            for (int i = 0; i < 4; i++) {
                unsigned long long ad = pk2(aa[i], aa[i]);
                c2[i][0] = fma2(ad, b01, c2[i][0]);
                c2[i][1] = fma2(ad, b23, c2[i][1]);
            }
        }
        __syncthreads();
    }

    const int col = n0 + (tx << 2);
    float4 bias = *reinterpret_cast<const float4*>(b1 + col);
    #pragma unroll
    for (int i = 0; i < 4; i++) {
        float r0, r1, r2, r3;
        upk2(c2[i][0], r0, r1);
        upk2(c2[i][1], r2, r3);
        float4 o;
        o.x = r0 + bias.x; o.y = r1 + bias.y; o.z = r2 + bias.z; o.w = r3 + bias.w;
        const int row = m0 + (ty << 2) + i;
        *reinterpret_cast<float4*>(g_z + (size_t)row * D_SZ + col) = o;
    }
}

// ============================================================================
// K3: per-feature partial sums / sumsq over 64-row chunks (coalesced).
// ============================================================================
__global__ void __launch_bounds__(256) stats_kernel() {
    const int d = threadIdx.x;
    const int r0 = blockIdx.x * (B_SZ / STAT_BLOCKS);
    float s = 0.f, sq = 0.f;
    #pragma unroll 4
    for (int r = 0; r < B_SZ / STAT_BLOCKS; r++) {
        float v = g_z[(size_t)(r0 + r) * D_SZ + d];
        s += v;
        sq = fmaf(v, v, sq);
    }
    g_psum[blockIdx.x * D_SZ + d] = s;
    g_psq[blockIdx.x * D_SZ + d] = sq;
}

// ============================================================================
// K4: finalize BN: scale = gamma*rstd, shift = beta - mu*scale.
// ============================================================================
__global__ void __launch_bounds__(256) finalize_stats_kernel(const float* __restrict__ gamma,
                                                             const float* __restrict__ beta) {
    const int d = threadIdx.x;
    float s = 0.f, sq = 0.f;
    #pragma unroll 4
    for (int i = 0; i < STAT_BLOCKS; i++) {
        s += g_psum[i * D_SZ + d];
        sq += g_psq[i * D_SZ + d];
    }
    const float mu = s * kInvB;
    const float var = sq * kInvB - mu * mu;
    const float rstd = rsqrtf(var + BN_EPS);
    const float sc = gamma[d] * rstd;
    g_scale[d] = sc;
    g_shift[d] = beta[d] - mu * sc;
}

// ============================================================================
// K5: h = relu(scale*z + shift); logit = h . w2 + b2   (one CTA per row)
// ============================================================================
__global__ void __launch_bounds__(256) head_kernel(const float* __restrict__ w2,
                                                   const float* __restrict__ b2,
                                                   float* __restrict__ out) {
    const int b = blockIdx.x;
    const int d = threadIdx.x;
    float v = g_z[(size_t)b * D_SZ + d];
    float h = fmaf(g_scale[d], v, g_shift[d]);
    h = fmaxf(h, 0.0f);
    float p = h * w2[d];

    __shared__ float red[256];
    red[d] = p;
    __syncthreads();
    #pragma unroll
    for (int s = 128; s > 0; s >>= 1) {
        if (d < s) red[d] += red[d + s];
        __syncthreads();
    }
    if (d == 0) out[1 + b] = red[0] + b2[0];
}

// ============================================================================
// K6: BCE-with-logits mean -> out[0].  Fixed-order tree reduction.
// ============================================================================
__global__ void __launch_bounds__(1024) loss_kernel(const float* __restrict__ t,
                                                    float* __restrict__ out) {
    const int tid = threadIdx.x;
    float s = 0.f;
    for (int i = tid; i < B_SZ; i += 1024) {
        float l = out[1 + i];
        float tv = t[i];
        s += fmaxf(l, 0.f) - l * tv + log1pf(expf(-fabsf(l)));
    }
    __shared__ float red[1024];
    red[tid] = s;
    __syncthreads();
    #pragma unroll
    for (int st = 512; st > 0; st >>= 1) {
        if (tid < st) red[tid] += red[tid + st];
        __syncthreads();
    }
    if (tid == 0) out[0] = red[0] * kInvB;
}

// ============================================================================
extern "C" void kernel_launch(void* const* d_in, const int* in_sizes, int n_in,
                              void* d_out, int out_size) {
    const int*   tokens  = (const int*)d_in[0];
    const int*   lengths = (const int*)d_in[1];
    const float* t       = (const float*)d_in[2];
    const float* emb     = (const float*)d_in[3];
    const float* W1      = (const float*)d_in[4];
    const float* b1      = (const float*)d_in[5];
    const float* gamma   = (const float*)d_in[6];
    const float* beta    = (const float*)d_in[7];
    const float* w2      = (const float*)d_in[8];
    const float* b2      = (const float*)d_in[9];
    float* out = (float*)d_out;

    pool_kernel<<<B_SZ, 256>>>(tokens, lengths, emb);
    gemm_kernel<<<dim3(B_SZ / 64, D_SZ / 64), 256>>>(W1, b1);
    stats_kernel<<<STAT_BLOCKS, 256>>>();
    finalize_stats_kernel<<<1, 256>>>(gamma, beta);
    head_kernel<<<B_SZ, 256>>>(w2, b2, out);
    loss_kernel<<<1, 1024>>>(t, out);
}

// round 3
// speedup vs baseline: 1.3079x; 1.3079x over previous
#include <cuda_runtime.h>
#include <math.h>

// Problem constants (fixed shapes from reference setup_inputs)
#define B_SZ 4096
#define L_SZ 200
#define D_SZ 256
#define MB_BLOCKS 64                // gemm m-tiles == BN partial count
static __device__ __constant__ float kInvB = 1.0f / (float)B_SZ;
#define BN_EPS 1e-5f

// ---- scratch (device globals; no allocation allowed) ----
__device__ float g_pooled[(size_t)B_SZ * D_SZ];   // 4 MB
__device__ float g_z[(size_t)B_SZ * D_SZ];        // 4 MB
__device__ float g_psum[MB_BLOCKS * D_SZ];
__device__ float g_psq[MB_BLOCKS * D_SZ];
__device__ float g_scale[D_SZ];
__device__ float g_shift[D_SZ];

// ---- packed f32x2 helpers (Blackwell) ----
__device__ __forceinline__ unsigned long long pk2(float lo, float hi) {
    unsigned long long r;
    asm("mov.b64 %0, {%1, %2};" : "=l"(r) : "f"(lo), "f"(hi));
    return r;
}
__device__ __forceinline__ void upk2(unsigned long long v, float& lo, float& hi) {
    asm("mov.b64 {%0, %1}, %2;" : "=f"(lo), "=f"(hi) : "l"(v));
}
__device__ __forceinline__ unsigned long long fma2(unsigned long long a,
                                                   unsigned long long b,
                                                   unsigned long long c) {
    unsigned long long d;
    asm("fma.rn.f32x2 %0, %1, %2, %3;" : "=l"(d) : "l"(a), "l"(b), "l"(c));
    return d;
}

// ============================================================================
// K1: ragged gather + mean pool.  One CTA per batch row, 256 threads.
// 4 tokens in flight x unroll-4 => up to 16 embedding rows outstanding/CTA.
// ============================================================================
__global__ void __launch_bounds__(256) pool_kernel(const int* __restrict__ tokens,
                                                   const int* __restrict__ lengths,
                                                   const float* __restrict__ emb) {
    const int b = blockIdx.x;
    const int tid = threadIdx.x;
    __shared__ int s_tok[L_SZ];
    const int len = lengths[b];
    for (int i = tid; i < len; i += 256) s_tok[i] = tokens[b * L_SZ + i];
    __syncthreads();

    const int sub = tid >> 6;   // 0..3 : which token of the group of 4
    const int q   = tid & 63;   // which float4 of the 256-wide embedding

    float4 acc = make_float4(0.f, 0.f, 0.f, 0.f);
    #pragma unroll 4
    for (int l = sub; l < len; l += 4) {
        const float4* row = reinterpret_cast<const float4*>(emb + (size_t)s_tok[l] * D_SZ);
        float4 v = __ldg(row + q);
        acc.x += v.x; acc.y += v.y; acc.z += v.z; acc.w += v.w;
    }

    __shared__ float4 s_acc[256];
    s_acc[tid] = acc;
    __syncthreads();
    if (tid < 64) {
        float4 a = s_acc[tid];
        float4 c = s_acc[tid + 64];
        float4 d = s_acc[tid + 128];
        float4 e = s_acc[tid + 192];
        const float inv = 1.0f / (float)len;
        float4 r;
        r.x = (a.x + c.x + d.x + e.x) * inv;
        r.y = (a.y + c.y + d.y + e.y) * inv;
        r.z = (a.z + c.z + d.z + e.z) * inv;
        r.w = (a.w + c.w + d.w + e.w) * inv;
        reinterpret_cast<float4*>(g_pooled + (size_t)b * D_SZ)[tid] = r;
    }
}

// ============================================================================
// K2: z = pooled @ W1^T + b1, PLUS per-tile BN partial stats in the epilogue.
// 64x64 block tile, BK=16, 256 threads, 4x4 per thread via fma.rn.f32x2.
// Epilogue: column sums/sumsq of the 64-row tile -> g_psum/g_psq[mb][feature].
// ============================================================================
__global__ void __launch_bounds__(256) gemm_kernel(const float* __restrict__ W1,
                                                   const float* __restrict__ b1) {
    __shared__ float As[16][68];   // As[k][m]  (+4 pad)
    __shared__ float Bs[16][68];   // Bs[k][n]
    __shared__ float s_sum[16][64];
    __shared__ float s_sq[16][64];

    const int tid = threadIdx.x;
    const int tx = tid & 15, ty = tid >> 4;
    const int m0 = blockIdx.x * 64;
    const int n0 = blockIdx.y * 64;
    const int lr = tid >> 2;            // 0..63 tile row
    const int lk = (tid & 3) << 2;      // 0,4,8,12 k-offset

    unsigned long long c2[4][2];
    #pragma unroll
    for (int i = 0; i < 4; i++) { c2[i][0] = 0ull; c2[i][1] = 0ull; }

    for (int k0 = 0; k0 < D_SZ; k0 += 16) {
        float4 av = *reinterpret_cast<const float4*>(g_pooled + (size_t)(m0 + lr) * D_SZ + k0 + lk);
        float4 bv = *reinterpret_cast<const float4*>(W1 + (size_t)(n0 + lr) * D_SZ + k0 + lk);
        As[lk + 0][lr] = av.x; As[lk + 1][lr] = av.y; As[lk + 2][lr] = av.z; As[lk + 3][lr] = av.w;
        Bs[lk + 0][lr] = bv.x; Bs[lk + 1][lr] = bv.y; Bs[lk + 2][lr] = bv.z; Bs[lk + 3][lr] = bv.w;
        __syncthreads();

        #pragma unroll
        for (int k = 0; k < 16; k++) {
            float4 a  = *reinterpret_cast<const float4*>(&As[k][ty << 2]);
            float4 bq = *reinterpret_cast<const float4*>(&Bs[k][tx << 2]);
            unsigned long long b01 = pk2(bq.x, bq.y);
            unsigned long long b23 = pk2(bq.z, bq.w);
            float aa[4] = {a.x, a.y, a.z, a.w};
            #pragma unroll
            for (int i = 0; i < 4; i++) {
                unsigned long long ad = pk2(aa[i], aa[i]);
                c2[i][0] = fma2(ad, b01, c2[i][0]);
                c2[i][1] = fma2(ad, b23, c2[i][1]);
            }
        }
        __syncthreads();
    }

    const int col = n0 + (tx << 2);
    float4 bias = *reinterpret_cast<const float4*>(b1 + col);
    float cs[4] = {0.f, 0.f, 0.f, 0.f};
    float cq[4] = {0.f, 0.f, 0.f, 0.f};
    #pragma unroll
    for (int i = 0; i < 4; i++) {
        float v[4];
        upk2(c2[i][0], v[0], v[1]);
        upk2(c2[i][1], v[2], v[3]);
        v[0] += bias.x; v[1] += bias.y; v[2] += bias.z; v[3] += bias.w;
        #pragma unroll
        for (int c = 0; c < 4; c++) {
            cs[c] += v[c];
            cq[c] = fmaf(v[c], v[c], cq[c]);
        }
        const int row = m0 + (ty << 2) + i;
        float4 o = make_float4(v[0], v[1], v[2], v[3]);
        *reinterpret_cast<float4*>(g_z + (size_t)row * D_SZ + col) = o;
    }
    // column partial stats: reduce over the 16 ty-groups
    #pragma unroll
    for (int c = 0; c < 4; c++) {
        s_sum[ty][(tx << 2) + c] = cs[c];
        s_sq[ty][(tx << 2) + c] = cq[c];
    }
    __syncthreads();
    if (tid < 64) {
        float s = 0.f, sq = 0.f;
        #pragma unroll
        for (int j = 0; j < 16; j++) { s += s_sum[j][tid]; sq += s_sq[j][tid]; }
        g_psum[blockIdx.x * D_SZ + n0 + tid] = s;
        g_psq[blockIdx.x * D_SZ + n0 + tid] = sq;
    }
}

// ============================================================================
// K3: finalize BN with 1024 threads: 4 slices x 256 features, SMEM combine.
// ============================================================================
__global__ void __launch_bounds__(1024) finalize_stats_kernel(const float* __restrict__ gamma,
                                                              const float* __restrict__ beta) {
    const int d = threadIdx.x & 255;
    const int j = threadIdx.x >> 8;       // 0..3
    float s = 0.f, sq = 0.f;
    #pragma unroll
    for (int i = 0; i < 16; i++) {
        const int chunk = j * 16 + i;
        s  += g_psum[chunk * D_SZ + d];
        sq += g_psq[chunk * D_SZ + d];
    }
    __shared__ float r_s[4][256];
    __shared__ float r_q[4][256];
    r_s[j][d] = s;
    r_q[j][d] = sq;
    __syncthreads();
    if (j == 0) {
        s  = r_s[0][d] + r_s[1][d] + r_s[2][d] + r_s[3][d];
        sq = r_q[0][d] + r_q[1][d] + r_q[2][d] + r_q[3][d];
        const float mu = s * kInvB;
        const float var = sq * kInvB - mu * mu;
        const float rstd = rsqrtf(var + BN_EPS);
        const float sc = gamma[d] * rstd;
        g_scale[d] = sc;
        g_shift[d] = beta[d] - mu * sc;
    }
}

// ============================================================================
// K4: h = relu(scale*z + shift); logit = h . w2 + b2.  Warp per row, 8 rows/CTA.
// ============================================================================
__global__ void __launch_bounds__(256) head_kernel(const float* __restrict__ w2,
                                                   const float* __restrict__ b2,
                                                   float* __restrict__ out) {
    const int warp = threadIdx.x >> 5;
    const int lane = threadIdx.x & 31;
    const int b = blockIdx.x * 8 + warp;

    const float4* zr = reinterpret_cast<const float4*>(g_z + (size_t)b * D_SZ);
    const float4* scv = reinterpret_cast<const float4*>(g_scale);
    const float4* shv = reinterpret_cast<const float4*>(g_shift);
    const float4* wv = reinterpret_cast<const float4*>(w2);

    float p = 0.f;
    #pragma unroll
    for (int half = 0; half < 2; half++) {
        const int q = lane + half * 32;
        float4 z = zr[q];
        float4 sc = __ldg(scv + q);
        float4 sh = __ldg(shv + q);
        float4 w = __ldg(wv + q);
        float h0 = fmaxf(fmaf(sc.x, z.x, sh.x), 0.f);
        float h1 = fmaxf(fmaf(sc.y, z.y, sh.y), 0.f);
        float h2 = fmaxf(fmaf(sc.z, z.z, sh.z), 0.f);
        float h3 = fmaxf(fmaf(sc.w, z.w, sh.w), 0.f);
        p += h0 * w.x + h1 * w.y + h2 * w.z + h3 * w.w;
    }
    #pragma unroll
    for (int off = 16; off > 0; off >>= 1)
        p += __shfl_down_sync(0xffffffffu, p, off);
    if (lane == 0) out[1 + b] = p + b2[0];
}

// ============================================================================
// K5: BCE-with-logits mean -> out[0].  Fixed-order tree reduction.
// ============================================================================
__global__ void __launch_bounds__(1024) loss_kernel(const float* __restrict__ t,
                                                    float* __restrict__ out) {
    const int tid = threadIdx.x;
    float s = 0.f;
    #pragma unroll 4
    for (int i = tid; i < B_SZ; i += 1024) {
        float l = out[1 + i];
        float tv = t[i];
        s += fmaxf(l, 0.f) - l * tv + log1pf(expf(-fabsf(l)));
    }
    __shared__ float red[1024];
    red[tid] = s;
    __syncthreads();
    #pragma unroll
    for (int st = 512; st > 0; st >>= 1) {
        if (tid < st) red[tid] += red[tid + st];
        __syncthreads();
    }
    if (tid == 0) out[0] = red[0] * kInvB;
}

// ============================================================================
extern "C" void kernel_launch(void* const* d_in, const int* in_sizes, int n_in,
                              void* d_out, int out_size) {
    const int*   tokens  = (const int*)d_in[0];
    const int*   lengths = (const int*)d_in[1];
    const float* t       = (const float*)d_in[2];
    const float* emb     = (const float*)d_in[3];
    const float* W1      = (const float*)d_in[4];
    const float* b1      = (const float*)d_in[5];
    const float* gamma   = (const float*)d_in[6];
    const float* beta    = (const float*)d_in[7];
    const float* w2      = (const float*)d_in[8];
    const float* b2      = (const float*)d_in[9];
    float* out = (float*)d_out;

    pool_kernel<<<B_SZ, 256>>>(tokens, lengths, emb);
    gemm_kernel<<<dim3(B_SZ / 64, D_SZ / 64), 256>>>(W1, b1);
    finalize_stats_kernel<<<1, 1024>>>(gamma, beta);
    head_kernel<<<B_SZ / 8, 256>>>(w2, b2, out);
    loss_kernel<<<1, 1024>>>(t, out);
}

// round 5
// speedup vs baseline: 1.3245x; 1.0127x over previous
#include <cuda_runtime.h>
#include <math.h>

// Problem constants (fixed shapes from reference setup_inputs)
#define B_SZ 4096
#define L_SZ 200
#define D_SZ 256
#define MB_BLOCKS 64                // gemm m-tiles == BN partial count
#define HEAD_CTAS (B_SZ / 8)        // 512
static __device__ __constant__ float kInvB = 1.0f / (float)B_SZ;
#define BN_EPS 1e-5f

// ---- scratch (device globals; no allocation allowed) ----
__device__ float g_pooled[(size_t)B_SZ * D_SZ];   // 4 MB
__device__ float g_z[(size_t)B_SZ * D_SZ];        // 4 MB
__device__ float g_psum[MB_BLOCKS * D_SZ];
__device__ float g_psq[MB_BLOCKS * D_SZ];
__device__ float g_scale[D_SZ];
__device__ float g_shift[D_SZ];
__device__ float g_bce[HEAD_CTAS];
__device__ unsigned int g_ctr_gemm;   // zero-initialized; last CTA resets
__device__ unsigned int g_ctr_head;

// ---- packed f32x2 helpers (Blackwell) ----
__device__ __forceinline__ unsigned long long pk2(float lo, float hi) {
    unsigned long long r;
    asm("mov.b64 %0, {%1, %2};" : "=l"(r) : "f"(lo), "f"(hi));
    return r;
}
__device__ __forceinline__ void upk2(unsigned long long v, float& lo, float& hi) {
    asm("mov.b64 {%0, %1}, %2;" : "=f"(lo), "=f"(hi) : "l"(v));
}
__device__ __forceinline__ unsigned long long fma2(unsigned long long a,
                                                   unsigned long long b,
                                                   unsigned long long c) {
    unsigned long long d;
    asm("fma.rn.f32x2 %0, %1, %2, %3;" : "=l"(d) : "l"(a), "l"(b), "l"(c));
    return d;
}

// ============================================================================
// K1: ragged gather + mean pool.  One CTA per batch row, 256 threads.
// 4 tokens in flight x unroll-4 => up to 16 embedding rows outstanding/CTA.
// ============================================================================
__global__ void __launch_bounds__(256) pool_kernel(const int* __restrict__ tokens,
                                                   const int* __restrict__ lengths,
                                                   const float* __restrict__ emb) {
    const int b = blockIdx.x;
    const int tid = threadIdx.x;
    __shared__ int s_tok[L_SZ];
    const int len = lengths[b];
    for (int i = tid; i < len; i += 256) s_tok[i] = tokens[b * L_SZ + i];
    __syncthreads();

    const int sub = tid >> 6;   // 0..3 : which token of the group of 4
    const int q   = tid & 63;   // which float4 of the 256-wide embedding

    float4 acc = make_float4(0.f, 0.f, 0.f, 0.f);
    #pragma unroll 4
    for (int l = sub; l < len; l += 4) {
        const float4* row = reinterpret_cast<const float4*>(emb + (size_t)s_tok[l] * D_SZ);
        float4 v = __ldg(row + q);
        acc.x += v.x; acc.y += v.y; acc.z += v.z; acc.w += v.w;
    }

    __shared__ float4 s_acc[256];
    s_acc[tid] = acc;
    __syncthreads();
    if (tid < 64) {
        float4 a = s_acc[tid];
        float4 c = s_acc[tid + 64];
        float4 d = s_acc[tid + 128];
        float4 e = s_acc[tid + 192];
        const float inv = 1.0f / (float)len;
        float4 r;
        r.x = (a.x + c.x + d.x + e.x) * inv;
        r.y = (a.y + c.y + d.y + e.y) * inv;
        r.z = (a.z + c.z + d.z + e.z) * inv;
        r.w = (a.w + c.w + d.w + e.w) * inv;
        reinterpret_cast<float4*>(g_pooled + (size_t)b * D_SZ)[tid] = r;
    }
}

// ============================================================================
// K2: z = pooled @ W1^T + b1 + BN partial stats in epilogue + LAST-CTA
// finalize (mu/var -> scale/shift).  64x64 tile, BK=16, 256 thr, f32x2 FMA.
// ============================================================================
__global__ void __launch_bounds__(256) gemm_kernel(const float* __restrict__ W1,
                                                   const float* __restrict__ b1,
                                                   const float* __restrict__ gamma,
                                                   const float* __restrict__ beta) {
    __shared__ float As[16][68];   // As[k][m]  (+4 pad)
    __shared__ float Bs[16][68];   // Bs[k][n]
    __shared__ float s_sum[16][64];
    __shared__ float s_sq[16][64];

    const int tid = threadIdx.x;
    const int tx = tid & 15, ty = tid >> 4;
    const int m0 = blockIdx.x * 64;
    const int n0 = blockIdx.y * 64;
    const int lr = tid >> 2;            // 0..63 tile row
    const int lk = (tid & 3) << 2;      // 0,4,8,12 k-offset

    unsigned long long c2[4][2];
    #pragma unroll
    for (int i = 0; i < 4; i++) { c2[i][0] = 0ull; c2[i][1] = 0ull; }

    for (int k0 = 0; k0 < D_SZ; k0 += 16) {
        float4 av = *reinterpret_cast<const float4*>(g_pooled + (size_t)(m0 + lr) * D_SZ + k0 + lk);
        float4 bv = *reinterpret_cast<const float4*>(W1 + (size_t)(n0 + lr) * D_SZ + k0 + lk);
        As[lk + 0][lr] = av.x; As[lk + 1][lr] = av.y; As[lk + 2][lr] = av.z; As[lk + 3][lr] = av.w;
        Bs[lk + 0][lr] = bv.x; Bs[lk + 1][lr] = bv.y; Bs[lk + 2][lr] = bv.z; Bs[lk + 3][lr] = bv.w;
        __syncthreads();

        #pragma unroll
        for (int k = 0; k < 16; k++) {
            float4 a  = *reinterpret_cast<const float4*>(&As[k][ty << 2]);
            float4 bq = *reinterpret_cast<const float4*>(&Bs[k][tx << 2]);
            unsigned long long b01 = pk2(bq.x, bq.y);
            unsigned long long b23 = pk2(bq.z, bq.w);
            float aa[4] = {a.x, a.y, a.z, a.w};
            #pragma unroll
            for (int i = 0; i < 4; i++) {
                unsigned long long ad = pk2(aa[i], aa[i]);
                c2[i][0] = fma2(ad, b01, c2[i][0]);
                c2[i][1] = fma2(ad, b23, c2[i][1]);
            }
        }
        __syncthreads();
    }

    const int col = n0 + (tx << 2);
    float4 bias = *reinterpret_cast<const float4*>(b1 + col);
    float cs[4] = {0.f, 0.f, 0.f, 0.f};
    float cq[4] = {0.f, 0.f, 0.f, 0.f};
    #pragma unroll
    for (int i = 0; i < 4; i++) {
        float v[4];
        upk2(c2[i][0], v[0], v[1]);
        upk2(c2[i][1], v[2], v[3]);
        v[0] += bias.x; v[1] += bias.y; v[2] += bias.z; v[3] += bias.w;
        #pragma unroll
        for (int c = 0; c < 4; c++) {
            cs[c] += v[c];
            cq[c] = fmaf(v[c], v[c], cq[c]);
        }
        const int row = m0 + (ty << 2) + i;
        float4 o = make_float4(v[0], v[1], v[2], v[3]);
        *reinterpret_cast<float4*>(g_z + (size_t)row * D_SZ + col) = o;
    }
    // column partial stats: reduce over the 16 ty-groups
    #pragma unroll
    for (int c = 0; c < 4; c++) {
        s_sum[ty][(tx << 2) + c] = cs[c];
        s_sq[ty][(tx << 2) + c] = cq[c];
    }
    __syncthreads();
    if (tid < 64) {
        float s = 0.f, sq = 0.f;
        #pragma unroll
        for (int j = 0; j < 16; j++) { s += s_sum[j][tid]; sq += s_sq[j][tid]; }
        g_psum[blockIdx.x * D_SZ + n0 + tid] = s;
        g_psq[blockIdx.x * D_SZ + n0 + tid] = sq;
    }

    // ---- last-CTA finalize: deterministic (fixed-order sums) ----
    __threadfence();
    __shared__ unsigned int s_ticket;
    if (tid == 0) s_ticket = atomicAdd(&g_ctr_gemm, 1u);
    __syncthreads();
    if (s_ticket == (unsigned)(gridDim.x * gridDim.y - 1)) {
        if (tid == 0) g_ctr_gemm = 0u;   // reset for next graph replay
        const int d = tid;               // 256 threads == 256 features
        float s = 0.f, sq = 0.f;
        #pragma unroll 8
        for (int i = 0; i < MB_BLOCKS; i++) {
            s  += g_psum[i * D_SZ + d];
            sq += g_psq[i * D_SZ + d];
        }
        const float mu = s * kInvB;
        const float var = sq * kInvB - mu * mu;
        const float rstd = rsqrtf(var + BN_EPS);
        const float sc = gamma[d] * rstd;
        g_scale[d] = sc;
        g_shift[d] = beta[d] - mu * sc;
    }
}

// ============================================================================
// K3: h = relu(scale*z + shift); logit = h.w2 + b2; per-CTA BCE partial;
// LAST CTA reduces 512 partials (fixed order) -> out[0].
// Warp per row, 8 rows/CTA, grid = 512.
// ============================================================================
__global__ void __launch_bounds__(256) head_kernel(const float* __restrict__ w2,
                                                   const float* __restrict__ b2,
                                                   const float* __restrict__ t,
                                                   float* __restrict__ out) {
    const int tid = threadIdx.x;
    const int warp = tid >> 5;
    const int lane = tid & 31;
    const int b = blockIdx.x * 8 + warp;

    const float4* zr = reinterpret_cast<const float4*>(g_z + (size_t)b * D_SZ);
    const float4* scv = reinterpret_cast<const float4*>(g_scale);
    const float4* shv = reinterpret_cast<const float4*>(g_shift);
    const float4* wv = reinterpret_cast<const float4*>(w2);

    float p = 0.f;
    #pragma unroll
    for (int half = 0; half < 2; half++) {
        const int q = lane + half * 32;
        float4 z = zr[q];
        float4 sc = __ldg(scv + q);
        float4 sh = __ldg(shv + q);
        float4 w = __ldg(wv + q);
        float h0 = fmaxf(fmaf(sc.x, z.x, sh.x), 0.f);
        float h1 = fmaxf(fmaf(sc.y, z.y, sh.y), 0.f);
        float h2 = fmaxf(fmaf(sc.z, z.z, sh.z), 0.f);
        float h3 = fmaxf(fmaf(sc.w, z.w, sh.w), 0.f);
        p += h0 * w.x + h1 * w.y + h2 * w.z + h3 * w.w;
    }
    #pragma unroll
    for (int off = 16; off > 0; off >>= 1)
        p += __shfl_down_sync(0xffffffffu, p, off);

    __shared__ float s_bce[8];
    if (lane == 0) {
        const float logit = p + b2[0];
        out[1 + b] = logit;
        const float tv = t[b];
        s_bce[warp] = fmaxf(logit, 0.f) - logit * tv + log1pf(expf(-fabsf(logit)));
    }
    __syncthreads();
    if (tid == 0) {
        float c = 0.f;
        #pragma unroll
        for (int i = 0; i < 8; i++) c += s_bce[i];
        g_bce[blockIdx.x] = c;
    }

    // ---- last-CTA loss reduce: deterministic fixed-order tree ----
    __threadfence();
    __shared__ unsigned int s_ticket;
    if (tid == 0) s_ticket = atomicAdd(&g_ctr_head, 1u);
    __syncthreads();
    if (s_ticket == (unsigned)(HEAD_CTAS - 1)) {
        if (tid == 0) g_ctr_head = 0u;   // reset for next graph replay
        __shared__ float red[256];
        red[tid] = g_bce[tid] + g_bce[tid + 256];
        __syncthreads();
        #pragma unroll
        for (int st = 128; st > 0; st >>= 1) {
            if (tid < st) red[tid] += red[tid + st];
            __syncthreads();
        }
        if (tid == 0) out[0] = red[0] * kInvB;
    }
}

// ============================================================================
extern "C" void kernel_launch(void* const* d_in, const int* in_sizes, int n_in,
                              void* d_out, int out_size) {
    const int*   tokens  = (const int*)d_in[0];
    const int*   lengths = (const int*)d_in[1];
    const float* t       = (const float*)d_in[2];
    const float* emb     = (const float*)d_in[3];
    const float* W1      = (const float*)d_in[4];
    const float* b1      = (const float*)d_in[5];
    const float* gamma   = (const float*)d_in[6];
    const float* beta    = (const float*)d_in[7];
    const float* w2      = (const float*)d_in[8];
    const float* b2      = (const float*)d_in[9];
    float* out = (float*)d_out;

    pool_kernel<<<B_SZ, 256>>>(tokens, lengths, emb);
    gemm_kernel<<<dim3(B_SZ / 64, D_SZ / 64), 256>>>(W1, b1, gamma, beta);
    head_kernel<<<HEAD_CTAS, 256>>>(w2, b2, t, out);
}